// round 8
// baseline (speedup 1.0000x reference)
#include <cuda_runtime.h>
#include <cuda_bf16.h>
#include <cstdint>
#include <math.h>

#define CB 4
#define CT 1024
#define CD 1024
#define CH 16
#define CHD 64
#define CL 8
#define CF 4096
#define CV 32000
#define CM (CB * CT)
#define QKVS (3 * CD)

typedef __nv_bfloat16 bf16;
typedef __nv_bfloat162 bf162;

// ---------------- scratch ----------------
__device__ float g_x[CM * CD];
__device__ float g_qkv[(size_t)CM * QKVS];
__device__ bf16 g_hh[CM * CD], g_hl[CM * CD];
__device__ bf16 g_yh[CM * CD], g_yl[CM * CD];
__device__ bf16 g_fh[(size_t)CM * CF], g_fl[(size_t)CM * CF];

__device__ bf16 t_qkvh[(size_t)CL * 3 * CD * CD], t_qkvl[(size_t)CL * 3 * CD * CD];
__device__ bf16 t_oh[(size_t)CL * CD * CD], t_ol[(size_t)CL * CD * CD];
__device__ bf16 t_1h[(size_t)CL * CF * CD], t_1l[(size_t)CL * CF * CD];
__device__ bf16 t_2h[(size_t)CL * CD * CF], t_2l[(size_t)CL * CD * CF];
__device__ bf16 t_hdh[(size_t)CV * CD], t_hdl[(size_t)CV * CD];

// ---------------- helpers ----------------
__device__ __forceinline__ uint32_t smem_u32(const void* p) {
    uint32_t a;
    asm("{ .reg .u64 t; cvta.to.shared.u64 t, %1; cvt.u32.u64 %0, t; }" : "=r"(a) : "l"(p));
    return a;
}
__device__ __forceinline__ void ldsm4(uint32_t* r, uint32_t addr) {
    asm volatile("ldmatrix.sync.aligned.m8n8.x4.shared.b16 {%0,%1,%2,%3}, [%4];"
                 : "=r"(r[0]), "=r"(r[1]), "=r"(r[2]), "=r"(r[3]) : "r"(addr));
}
__device__ __forceinline__ void mma16816(float* d, const uint32_t* a, const uint32_t* b) {
    asm volatile(
        "mma.sync.aligned.m16n8k16.row.col.f32.bf16.bf16.f32 "
        "{%0,%1,%2,%3}, {%4,%5,%6,%7}, {%8,%9}, {%0,%1,%2,%3};"
        : "+f"(d[0]), "+f"(d[1]), "+f"(d[2]), "+f"(d[3])
        : "r"(a[0]), "r"(a[1]), "r"(a[2]), "r"(a[3]), "r"(b[0]), "r"(b[1]));
}
__device__ __forceinline__ void cp16(uint32_t smem, const void* g) {
    asm volatile("cp.async.cg.shared.global [%0], [%1], 16;" :: "r"(smem), "l"(g));
}
#define CP_COMMIT() asm volatile("cp.async.commit_group;" ::: "memory")
#define CP_WAIT1()  asm volatile("cp.async.wait_group 1;" ::: "memory")

__device__ __forceinline__ float gelu_f(float v) {
    return 0.5f * v * (1.0f + erff(v * 0.70710678118654752f));
}
__device__ __forceinline__ void split_bf(float x, bf16& hi, bf16& lo) {
    hi = __float2bfloat16(x);
    lo = __float2bfloat16(x - __bfloat162float(hi));
}

// ---------------- embedding ----------------
__global__ __launch_bounds__(256) void embed_kernel(
    const int* __restrict__ idx, const float* __restrict__ tok,
    const float* __restrict__ pos, float* __restrict__ x)
{
    int row = blockIdx.x, tid = threadIdx.x;
    int t = row & (CT - 1);
    int token = idx[row];
    float4 a = ((const float4*)(tok + (size_t)token * CD))[tid];
    float4 p = ((const float4*)(pos + (size_t)t * CD))[tid];
    float4 o;
    o.x = a.x + p.x; o.y = a.y + p.y; o.z = a.z + p.z; o.w = a.w + p.w;
    ((float4*)(x + (size_t)row * CD))[tid] = o;
}

// ---------------- LayerNorm -> bf16 hi/lo planes ----------------
__global__ __launch_bounds__(256) void ln_split_kernel(
    const float* __restrict__ x, const float* __restrict__ g,
    const float* __restrict__ b, bf16* __restrict__ hh, bf16* __restrict__ hl)
{
    int row = blockIdx.x, tid = threadIdx.x;
    float4 v = ((const float4*)(x + (size_t)row * CD))[tid];

    __shared__ float red[8];
    __shared__ float bcast;

    float s = v.x + v.y + v.z + v.w;
    #pragma unroll
    for (int o = 16; o > 0; o >>= 1) s += __shfl_xor_sync(0xffffffffu, s, o);
    if ((tid & 31) == 0) red[tid >> 5] = s;
    __syncthreads();
    if (tid == 0) {
        float t = 0.f;
        #pragma unroll
        for (int i = 0; i < 8; i++) t += red[i];
        bcast = t * (1.0f / CD);
    }
    __syncthreads();
    float mean = bcast;
    __syncthreads();

    float dx = v.x - mean, dy = v.y - mean, dz = v.z - mean, dw = v.w - mean;
    float s2 = dx * dx + dy * dy + dz * dz + dw * dw;
    #pragma unroll
    for (int o = 16; o > 0; o >>= 1) s2 += __shfl_xor_sync(0xffffffffu, s2, o);
    if ((tid & 31) == 0) red[tid >> 5] = s2;
    __syncthreads();
    if (tid == 0) {
        float t = 0.f;
        #pragma unroll
        for (int i = 0; i < 8; i++) t += red[i];
        bcast = rsqrtf(t * (1.0f / CD) + 1e-5f);
    }
    __syncthreads();
    float rs = bcast;

    float4 gg = ((const float4*)g)[tid];
    float4 bb = ((const float4*)b)[tid];
    float o0 = dx * rs * gg.x + bb.x;
    float o1 = dy * rs * gg.y + bb.y;
    float o2 = dz * rs * gg.z + bb.z;
    float o3 = dw * rs * gg.w + bb.w;

    bf16 h0, l0, h1, l1, h2, l2, h3, l3;
    split_bf(o0, h0, l0); split_bf(o1, h1, l1);
    split_bf(o2, h2, l2); split_bf(o3, h3, l3);
    bf162* H = (bf162*)(hh + (size_t)row * CD);
    bf162* L = (bf162*)(hl + (size_t)row * CD);
    bf162 a01, a23, c01, c23;
    a01.x = h0; a01.y = h1; a23.x = h2; a23.y = h3;
    c01.x = l0; c01.y = l1; c23.x = l2; c23.y = l3;
    H[2 * tid] = a01; H[2 * tid + 1] = a23;
    L[2 * tid] = c01; L[2 * tid + 1] = c23;
}

// ---------------- transpose+split core ----------------
__device__ __forceinline__ void tsplit_body(
    const float* __restrict__ W, bf16* __restrict__ Th, bf16* __restrict__ Tl,
    int K, int N, int n0, int k0)
{
    __shared__ float t[64][65];
    int tid = threadIdx.x;

    int lr = tid >> 4;
    int lc = (tid & 15) << 2;
    #pragma unroll
    for (int s = 0; s < 4; s++) {
        int k = s * 16 + lr;
        float4 v = *(const float4*)(W + (size_t)(k0 + k) * N + n0 + lc);
        t[k][lc] = v.x; t[k][lc + 1] = v.y; t[k][lc + 2] = v.z; t[k][lc + 3] = v.w;
    }
    __syncthreads();

    int n = tid >> 2;
    int kb = (tid & 3) << 4;
    __align__(16) bf16 hi[16];
    __align__(16) bf16 lo[16];
    #pragma unroll
    for (int i = 0; i < 16; i++)
        split_bf(t[kb + i][n], hi[i], lo[i]);
    size_t o = (size_t)(n0 + n) * K + k0 + kb;
    *(uint4*)(Th + o)     = *(uint4*)&hi[0];
    *(uint4*)(Th + o + 8) = *(uint4*)&hi[8];
    *(uint4*)(Tl + o)     = *(uint4*)&lo[0];
    *(uint4*)(Tl + o + 8) = *(uint4*)&lo[8];
}

__global__ __launch_bounds__(256) void tsplit_batch_kernel(
    const float* __restrict__ W, bf16* __restrict__ Th, bf16* __restrict__ Tl,
    int K, int N)
{
    size_t off = (size_t)blockIdx.z * K * N;
    tsplit_body(W + off, Th + off, Tl + off, K, N, blockIdx.x * 64, blockIdx.y * 64);
}

__global__ __launch_bounds__(256) void tsplit_qkv_kernel(
    const float* __restrict__ wq, const float* __restrict__ wk,
    const float* __restrict__ wv, bf16* __restrict__ Th, bf16* __restrict__ Tl)
{
    int z = blockIdx.z;
    int l = z / 3, m = z - 3 * l;
    const float* W = (m == 0 ? wq : (m == 1 ? wk : wv)) + (size_t)l * CD * CD;
    size_t dofs = (size_t)l * 3 * CD * CD + (size_t)m * CD * CD;
    tsplit_body(W, Th + dofs, Tl + dofs, CD, CD, blockIdx.x * 64, blockIdx.y * 64);
}

// ---------------- HMMA bf16x3 GEMM ----------------
// CTA tile 128x256, BK=32, 8 warps (2m x 4n), warp tile 64x64.
// 3-stage cp.async, 48KB/stage (Ah 8K | Al 8K | Bh 16K | Bl 16K), 1 CTA/SM.
#define STG 49152
#define GEMM_SMEM (3 * STG)
#define GEMM_THR 256

__device__ __forceinline__ void gemm_load_stage(
    const bf16* Ah, const bf16* Al, const bf16* Bh, const bf16* Bl,
    int m0, int n0, int K, int k0, uint32_t st, int tid)
{
    #pragma unroll
    for (int i = 0; i < 12; i++) {
        int g = i * GEMM_THR + tid;      // 0..3071 chunks of 16B
        const bf16* src;
        uint32_t off;
        if (i < 4) {                      // g < 1024: A planes
            int t4 = g >> 9;              // 0 Ah, 1 Al
            int r = (g >> 2) & 127;
            int c = g & 3;
            src = (t4 ? Al : Ah) + (size_t)(m0 + r) * K + k0 + c * 8;
            off = ((uint32_t)t4 << 13) + (r << 6) + (((uint32_t)(c ^ ((r >> 1) & 3))) << 4);
        } else {                          // B planes
            int gb = g - 1024;
            int t4 = gb >> 10;            // 0 Bh, 1 Bl
            int r = (gb >> 2) & 255;
            int c = gb & 3;
            src = (t4 ? Bl : Bh) + (size_t)(n0 + r) * K + k0 + c * 8;
            off = 16384u + ((uint32_t)t4 << 14) + (r << 6) +
                  (((uint32_t)(c ^ ((r >> 1) & 3))) << 4);
        }
        cp16(st + off, src);
    }
}

// EPI: 0 plain fp32 | 1 bias+res fp32 | 2 bias+GELU -> bf16 planes | 3 bias fp32
template<int EPI>
__global__ __launch_bounds__(GEMM_THR, 1) void gemm_mma(
    const bf16* __restrict__ Ah, const bf16* __restrict__ Al,
    const bf16* __restrict__ Bh, const bf16* __restrict__ Bl,
    const float* __restrict__ bias, const float* __restrict__ res,
    float* __restrict__ C, bf16* __restrict__ Ch, bf16* __restrict__ Cl,
    int N, int K)
{
    extern __shared__ char smraw[];
    uint32_t sbase = smem_u32(smraw);

    const int tid = threadIdx.x;
    const int m0 = blockIdx.x * 128, n0 = blockIdx.y * 256;
    const int lane = tid & 31, warp = tid >> 5;
    const int wm = (warp >> 2) * 64, wn = (warp & 3) * 64;

    float acc[4][8][4];
    #pragma unroll
    for (int a = 0; a < 4; a++)
        #pragma unroll
        for (int b = 0; b < 8; b++)
            #pragma unroll
            for (int c = 0; c < 4; c++) acc[a][b][c] = 0.f;

    const int NI = K / 32;

    gemm_load_stage(Ah, Al, Bh, Bl, m0, n0, K, 0, sbase, tid);
    CP_COMMIT();
    gemm_load_stage(Ah, Al, Bh, Bl, m0, n0, K, 32, sbase + STG, tid);
    CP_COMMIT();

    int b2 = 2;
    for (int it = 0; it < NI; it++) {
        CP_WAIT1();
        __syncthreads();
        if (it + 2 < NI)
            gemm_load_stage(Ah, Al, Bh, Bl, m0, n0, K, (it + 2) * 32,
                            sbase + b2 * STG, tid);
        CP_COMMIT();
        if (++b2 == 3) b2 = 0;

        uint32_t st = sbase + (it - (it / 3) * 3) * STG;
        #pragma unroll
        for (int c16 = 0; c16 < 2; c16++) {
            uint32_t bH[4][4], bL[4][4];
            #pragma unroll
            for (int jj = 0; jj < 4; jj++) {
                int q = lane >> 3;
                int nr = wn + (jj * 2 + (q >> 1)) * 8 + (lane & 7);
                int ch = (2 * c16 + (q & 1)) ^ ((nr >> 1) & 3);
                uint32_t ad = st + 16384 + (nr << 6) + (ch << 4);
                ldsm4(bH[jj], ad);
                ldsm4(bL[jj], ad + 16384);
            }
            #pragma unroll
            for (int mi = 0; mi < 4; mi++) {
                uint32_t aH[4], aL[4];
                int row = wm + mi * 16 + (lane & 15);
                int ch = (2 * c16 + (lane >> 4)) ^ ((row >> 1) & 3);
                uint32_t ad = st + (row << 6) + (ch << 4);
                ldsm4(aH, ad);
                ldsm4(aL, ad + 8192);
                #pragma unroll
                for (int ni = 0; ni < 8; ni++) {
                    const uint32_t* bh = &bH[ni >> 1][(ni & 1) * 2];
                    const uint32_t* bl = &bL[ni >> 1][(ni & 1) * 2];
                    mma16816(acc[mi][ni], aH, bh);
                    mma16816(acc[mi][ni], aL, bh);
                    mma16816(acc[mi][ni], aH, bl);
                }
            }
        }
    }

    // ---------------- epilogue ----------------
    #pragma unroll
    for (int mi = 0; mi < 4; mi++) {
        #pragma unroll
        for (int ni = 0; ni < 8; ni++) {
            int r0 = m0 + wm + mi * 16 + (lane >> 2);
            int cg = n0 + wn + ni * 8 + (lane & 3) * 2;
            float v0 = acc[mi][ni][0], v1 = acc[mi][ni][1];
            float v2 = acc[mi][ni][2], v3 = acc[mi][ni][3];
            if (EPI == 1 || EPI == 2 || EPI == 3) {
                float b0 = bias[cg], b1 = bias[cg + 1];
                v0 += b0; v1 += b1; v2 += b0; v3 += b1;
            }
            if (EPI == 2) {
                v0 = gelu_f(v0); v1 = gelu_f(v1);
                v2 = gelu_f(v2); v3 = gelu_f(v3);
                bf16 h0, l0, h1, l1;
                bf162 hp, lp;
                split_bf(v0, h0, l0); split_bf(v1, h1, l1);
                hp.x = h0; hp.y = h1; lp.x = l0; lp.y = l1;
                *(bf162*)(Ch + (size_t)r0 * N + cg) = hp;
                *(bf162*)(Cl + (size_t)r0 * N + cg) = lp;
                split_bf(v2, h0, l0); split_bf(v3, h1, l1);
                hp.x = h0; hp.y = h1; lp.x = l0; lp.y = l1;
                *(bf162*)(Ch + (size_t)(r0 + 8) * N + cg) = hp;
                *(bf162*)(Cl + (size_t)(r0 + 8) * N + cg) = lp;
            } else {
                if (EPI == 1) {
                    float2 ra = *(const float2*)(res + (size_t)r0 * N + cg);
                    float2 rb = *(const float2*)(res + (size_t)(r0 + 8) * N + cg);
                    v0 += ra.x; v1 += ra.y; v2 += rb.x; v3 += rb.y;
                }
                float2 w0, w1;
                w0.x = v0; w0.y = v1; w1.x = v2; w1.y = v3;
                *(float2*)(C + (size_t)r0 * N + cg) = w0;
                *(float2*)(C + (size_t)(r0 + 8) * N + cg) = w1;
            }
        }
    }
}

// ---------------- flash attention (fp32, packed QKV input) ----------------
__global__ __launch_bounds__(256) void attn_kernel(
    const float* __restrict__ QKV, bf16* __restrict__ Yh, bf16* __restrict__ Yl)
{
    extern __shared__ float sm[];
    float* Qst = sm;
    float* Kst = sm + 64 * 64;
    float* Vs  = sm + 2 * 64 * 64;
    float* Pst = sm + 3 * 64 * 64;

    int tid = threadIdx.x;
    int qt = blockIdx.x;
    int bh = blockIdx.y;
    int b = bh >> 4, h = bh & 15;
    int rt = tid >> 4, ct = tid & 15;
    int li = tid >> 2, lf = tid & 3;
    const float scale = 0.125f;

    {
        int t = qt * 64 + li;
        const float* qrow = QKV + (size_t)(b * CT + t) * QKVS + h * CHD;
        #pragma unroll
        for (int u = 0; u < 4; u++) {
            int d4 = lf * 16 + u * 4;
            float4 v = *(const float4*)(qrow + d4);
            Qst[(d4 + 0) * 64 + li] = v.x * scale;
            Qst[(d4 + 1) * 64 + li] = v.y * scale;
            Qst[(d4 + 2) * 64 + li] = v.z * scale;
            Qst[(d4 + 3) * 64 + li] = v.w * scale;
        }
    }

    float m_i[4], l_i[4], o[4][4];
    #pragma unroll
    for (int i = 0; i < 4; i++) {
        m_i[i] = -1e30f; l_i[i] = 0.f;
        #pragma unroll
        for (int d = 0; d < 4; d++) o[i][d] = 0.f;
    }

    for (int kt = 0; kt <= qt; kt++) {
        __syncthreads();
        {
            int t = kt * 64 + li;
            const float* krow = QKV + (size_t)(b * CT + t) * QKVS + CD + h * CHD;
            const float* vrow = QKV + (size_t)(b * CT + t) * QKVS + 2 * CD + h * CHD;
            #pragma unroll
            for (int u = 0; u < 4; u++) {
                int d4 = lf * 16 + u * 4;
                float4 kv = *(const float4*)(krow + d4);
                Kst[(d4 + 0) * 64 + li] = kv.x;
                Kst[(d4 + 1) * 64 + li] = kv.y;
                Kst[(d4 + 2) * 64 + li] = kv.z;
                Kst[(d4 + 3) * 64 + li] = kv.w;
                *(float4*)&Vs[li * 64 + d4] = *(const float4*)(vrow + d4);
            }
        }
        __syncthreads();

        float s[4][4];
        #pragma unroll
        for (int i = 0; i < 4; i++)
            #pragma unroll
            for (int j = 0; j < 4; j++) s[i][j] = 0.f;
        for (int d = 0; d < 64; d++) {
            float a[4], bb[4];
            *(float4*)a  = *(const float4*)&Qst[d * 64 + rt * 4];
            *(float4*)bb = *(const float4*)&Kst[d * 64 + ct * 4];
            #pragma unroll
            for (int i = 0; i < 4; i++)
                #pragma unroll
                for (int j = 0; j < 4; j++)
                    s[i][j] = fmaf(a[i], bb[j], s[i][j]);
        }

        if (kt == qt) {
            #pragma unroll
            for (int i = 0; i < 4; i++)
                #pragma unroll
                for (int j = 0; j < 4; j++)
                    if (ct * 4 + j > rt * 4 + i) s[i][j] = -1e30f;
        }

        #pragma unroll
        for (int i = 0; i < 4; i++) {
            float mx = fmaxf(fmaxf(s[i][0], s[i][1]), fmaxf(s[i][2], s[i][3]));
            #pragma unroll
            for (int off = 1; off < 16; off <<= 1)
                mx = fmaxf(mx, __shfl_xor_sync(0xffffffffu, mx, off));
            float mn = fmaxf(m_i[i], mx);
            float sc = __expf(m_i[i] - mn);
            m_i[i] = mn;
            float ps = 0.f;
            #pragma unroll
            for (int j = 0; j < 4; j++) {
                float p = __expf(s[i][j] - mn);
                s[i][j] = p;
                ps += p;
            }
            #pragma unroll
            for (int off = 1; off < 16; off <<= 1)
                ps += __shfl_xor_sync(0xffffffffu, ps, off);
            l_i[i] = l_i[i] * sc + ps;
            #pragma unroll
            for (int d = 0; d < 4; d++) o[i][d] *= sc;
        }

        #pragma unroll
        for (int i = 0; i < 4; i++)
            #pragma unroll
            for (int j = 0; j < 4; j++)
                Pst[(ct * 4 + j) * 64 + rt * 4 + i] = s[i][j];
        __syncthreads();

        for (int j = 0; j < 64; j++) {
            float p[4], vv[4];
            *(float4*)p  = *(const float4*)&Pst[j * 64 + rt * 4];
            *(float4*)vv = *(const float4*)&Vs[j * 64 + ct * 4];
            #pragma unroll
            for (int i = 0; i < 4; i++)
                #pragma unroll
                for (int d = 0; d < 4; d++)
                    o[i][d] = fmaf(p[i], vv[d], o[i][d]);
        }
    }

    #pragma unroll
    for (int i = 0; i < 4; i++) {
        int t = qt * 64 + rt * 4 + i;
        float inv = 1.0f / l_i[i];
        size_t off = (size_t)(b * CT + t) * CD + h * CHD + ct * 4;
        bf16 h0, l0, h1, l1, h2, l2, h3, l3;
        split_bf(o[i][0] * inv, h0, l0);
        split_bf(o[i][1] * inv, h1, l1);
        split_bf(o[i][2] * inv, h2, l2);
        split_bf(o[i][3] * inv, h3, l3);
        bf162 a01, a23, c01, c23;
        a01.x = h0; a01.y = h1; a23.x = h2; a23.y = h3;
        c01.x = l0; c01.y = l1; c23.x = l2; c23.y = l3;
        ((bf162*)(Yh + off))[0] = a01; ((bf162*)(Yh + off))[1] = a23;
        ((bf162*)(Yl + off))[0] = c01; ((bf162*)(Yl + off))[1] = c23;
    }
}

// ---------------- host ----------------
extern "C" void kernel_launch(void* const* d_in, const int* in_sizes, int n_in,
                              void* d_out, int out_size)
{
    (void)in_sizes; (void)n_in; (void)out_size;

    const int*   idx     = (const int*)  d_in[0];
    const float* tok_emb = (const float*)d_in[1];
    const float* pos_emb = (const float*)d_in[2];
    const float* wq      = (const float*)d_in[3];
    const float* wk      = (const float*)d_in[4];
    const float* wv      = (const float*)d_in[5];
    const float* wo      = (const float*)d_in[6];
    const float* bo      = (const float*)d_in[7];
    const float* ln1_g   = (const float*)d_in[8];
    const float* ln1_b   = (const float*)d_in[9];
    const float* ln2_g   = (const float*)d_in[10];
    const float* ln2_b   = (const float*)d_in[11];
    const float* w1      = (const float*)d_in[12];
    const float* b1      = (const float*)d_in[13];
    const float* w2      = (const float*)d_in[14];
    const float* b2      = (const float*)d_in[15];
    const float* lnf_g   = (const float*)d_in[16];
    const float* lnf_b   = (const float*)d_in[17];
    const float* w_head  = (const float*)d_in[18];
    const float* b_head  = (const float*)d_in[19];
    float* out = (float*)d_out;

    float *x, *qkv;
    bf16 *hh, *hl, *yh, *yl, *fh, *fl;
    bf16 *qkvh, *qkvl, *oh, *ol, *h1h, *h1l, *h2h, *h2l, *hdh, *hdl;
    cudaGetSymbolAddress((void**)&x, g_x);
    cudaGetSymbolAddress((void**)&qkv, g_qkv);
    cudaGetSymbolAddress((void**)&hh, g_hh);
    cudaGetSymbolAddress((void**)&hl, g_hl);
    cudaGetSymbolAddress((void**)&yh, g_yh);
    cudaGetSymbolAddress((void**)&yl, g_yl);
    cudaGetSymbolAddress((void**)&fh, g_fh);
    cudaGetSymbolAddress((void**)&fl, g_fl);
    cudaGetSymbolAddress((void**)&qkvh, t_qkvh);
    cudaGetSymbolAddress((void**)&qkvl, t_qkvl);
    cudaGetSymbolAddress((void**)&oh, t_oh);
    cudaGetSymbolAddress((void**)&ol, t_ol);
    cudaGetSymbolAddress((void**)&h1h, t_1h);
    cudaGetSymbolAddress((void**)&h1l, t_1l);
    cudaGetSymbolAddress((void**)&h2h, t_2h);
    cudaGetSymbolAddress((void**)&h2l, t_2l);
    cudaGetSymbolAddress((void**)&hdh, t_hdh);
    cudaGetSymbolAddress((void**)&hdl, t_hdl);

    cudaFuncSetAttribute(attn_kernel, cudaFuncAttributeMaxDynamicSharedMemorySize, 65536);
    cudaFuncSetAttribute(gemm_mma<0>, cudaFuncAttributeMaxDynamicSharedMemorySize, GEMM_SMEM);
    cudaFuncSetAttribute(gemm_mma<1>, cudaFuncAttributeMaxDynamicSharedMemorySize, GEMM_SMEM);
    cudaFuncSetAttribute(gemm_mma<2>, cudaFuncAttributeMaxDynamicSharedMemorySize, GEMM_SMEM);
    cudaFuncSetAttribute(gemm_mma<3>, cudaFuncAttributeMaxDynamicSharedMemorySize, GEMM_SMEM);

    dim3 gQKV(CM / 128, QKVS / 256);  // (32, 12)
    dim3 gDD(CM / 128, CD / 256);     // (32, 4)
    dim3 gDF(CM / 128, CF / 256);     // (32, 16)
    dim3 gDV(CM / 128, CV / 256);     // (32, 125)
    dim3 gAt(CT / 64, CB * CH);

    // launch 0: qkv weight planes (needed by launch 3)
    tsplit_qkv_kernel<<<dim3(CD / 64, CD / 64, 3 * CL), 256>>>(wq, wk, wv, qkvh, qkvl);
    // launch 1, 2
    embed_kernel<<<CM, 256>>>(idx, tok_emb, pos_emb, x);
    ln_split_kernel<<<CM, 256>>>(x, ln1_g, ln1_b, hh, hl);
    // launch 3: profiled — layer-0 QKV GEMM
    gemm_mma<0><<<gQKV, GEMM_THR, GEMM_SMEM>>>(hh, hl, qkvh, qkvl,
                                               nullptr, nullptr, qkv, nullptr, nullptr,
                                               QKVS, CD);
    // remaining prepass (batched)
    tsplit_batch_kernel<<<dim3(CD / 64, CD / 64, CL), 256>>>(wo, oh, ol, CD, CD);
    tsplit_batch_kernel<<<dim3(CF / 64, CD / 64, CL), 256>>>(w1, h1h, h1l, CD, CF);
    tsplit_batch_kernel<<<dim3(CD / 64, CF / 64, CL), 256>>>(w2, h2h, h2l, CF, CD);
    tsplit_batch_kernel<<<dim3(CV / 64, CD / 64, 1), 256>>>(w_head, hdh, hdl, CD, CV);

    for (int l = 0; l < CL; l++) {
        size_t wo4 = (size_t)l * CD * CD;
        size_t p3 = (size_t)l * 3 * CD * CD;
        size_t w1o = (size_t)l * CD * CF;
        if (l > 0) {
            ln_split_kernel<<<CM, 256>>>(x, ln1_g + l * CD, ln1_b + l * CD, hh, hl);
            gemm_mma<0><<<gQKV, GEMM_THR, GEMM_SMEM>>>(hh, hl, qkvh + p3, qkvl + p3,
                                                       nullptr, nullptr, qkv, nullptr, nullptr,
                                                       QKVS, CD);
        }
        attn_kernel<<<gAt, 256, 65536>>>(qkv, yh, yl);
        gemm_mma<1><<<gDD, GEMM_THR, GEMM_SMEM>>>(yh, yl, oh + wo4, ol + wo4,
                                                  bo + l * CD, x, x, nullptr, nullptr, CD, CD);
        ln_split_kernel<<<CM, 256>>>(x, ln2_g + l * CD, ln2_b + l * CD, hh, hl);
        gemm_mma<2><<<gDF, GEMM_THR, GEMM_SMEM>>>(hh, hl, h1h + w1o, h1l + w1o,
                                                  b1 + (size_t)l * CF, nullptr,
                                                  nullptr, fh, fl, CF, CD);
        gemm_mma<1><<<gDD, GEMM_THR, GEMM_SMEM>>>(fh, fl, h2h + w1o, h2l + w1o,
                                                  b2 + l * CD, x, x, nullptr, nullptr, CD, CF);
    }

    ln_split_kernel<<<CM, 256>>>(x, lnf_g, lnf_b, hh, hl);
    gemm_mma<3><<<gDV, GEMM_THR, GEMM_SMEM>>>(hh, hl, hdh, hdl,
                                              b_head, nullptr, out, nullptr, nullptr, CV, CD);
}

// round 10
// speedup vs baseline: 1.0936x; 1.0936x over previous
#include <cuda_runtime.h>
#include <cuda_bf16.h>
#include <cstdint>
#include <math.h>

#define CB 4
#define CT 1024
#define CD 1024
#define CH 16
#define CHD 64
#define CL 8
#define CF 4096
#define CV 32000
#define CM (CB * CT)
#define QKVS (3 * CD)

typedef __nv_bfloat16 bf16;
typedef __nv_bfloat162 bf162;

// ---------------- scratch ----------------
__device__ float g_x[CM * CD];
__device__ float g_qkv[(size_t)CM * QKVS];
__device__ bf16 g_hh[CM * CD], g_hl[CM * CD];
__device__ bf16 g_yh[CM * CD], g_yl[CM * CD];
__device__ bf16 g_fh[(size_t)CM * CF], g_fl[(size_t)CM * CF];

__device__ bf16 t_qkvh[(size_t)CL * 3 * CD * CD], t_qkvl[(size_t)CL * 3 * CD * CD];
__device__ bf16 t_oh[(size_t)CL * CD * CD], t_ol[(size_t)CL * CD * CD];
__device__ bf16 t_1h[(size_t)CL * CF * CD], t_1l[(size_t)CL * CF * CD];
__device__ bf16 t_2h[(size_t)CL * CD * CF], t_2l[(size_t)CL * CD * CF];
__device__ bf16 t_hdh[(size_t)CV * CD], t_hdl[(size_t)CV * CD];

// ---------------- helpers ----------------
__device__ __forceinline__ uint32_t smem_u32(const void* p) {
    uint32_t a;
    asm("{ .reg .u64 t; cvta.to.shared.u64 t, %1; cvt.u32.u64 %0, t; }" : "=r"(a) : "l"(p));
    return a;
}
__device__ __forceinline__ void ldsm4(uint32_t* r, uint32_t addr) {
    asm volatile("ldmatrix.sync.aligned.m8n8.x4.shared.b16 {%0,%1,%2,%3}, [%4];"
                 : "=r"(r[0]), "=r"(r[1]), "=r"(r[2]), "=r"(r[3]) : "r"(addr));
}
__device__ __forceinline__ void mma16816(float* d, const uint32_t* a, const uint32_t* b) {
    asm volatile(
        "mma.sync.aligned.m16n8k16.row.col.f32.bf16.bf16.f32 "
        "{%0,%1,%2,%3}, {%4,%5,%6,%7}, {%8,%9}, {%0,%1,%2,%3};"
        : "+f"(d[0]), "+f"(d[1]), "+f"(d[2]), "+f"(d[3])
        : "r"(a[0]), "r"(a[1]), "r"(a[2]), "r"(a[3]), "r"(b[0]), "r"(b[1]));
}
__device__ __forceinline__ void cp16(uint32_t smem, const void* g) {
    asm volatile("cp.async.cg.shared.global [%0], [%1], 16;" :: "r"(smem), "l"(g));
}
#define CP_COMMIT() asm volatile("cp.async.commit_group;" ::: "memory")
#define CP_WAIT1()  asm volatile("cp.async.wait_group 1;" ::: "memory")

__device__ __forceinline__ float gelu_f(float v) {
    return 0.5f * v * (1.0f + erff(v * 0.70710678118654752f));
}
__device__ __forceinline__ void split_bf(float x, bf16& hi, bf16& lo) {
    hi = __float2bfloat16(x);
    lo = __float2bfloat16(x - __bfloat162float(hi));
}

// ---------------- LN body (shared by ln_split and embed_ln) ----------------
__device__ __forceinline__ void ln_rows_body(
    float4 v, const float* __restrict__ g, const float* __restrict__ b,
    bf16* __restrict__ hh, bf16* __restrict__ hl, int row, int tid)
{
    __shared__ float red[8];
    __shared__ float bcast;

    float s = v.x + v.y + v.z + v.w;
    #pragma unroll
    for (int o = 16; o > 0; o >>= 1) s += __shfl_xor_sync(0xffffffffu, s, o);
    if ((tid & 31) == 0) red[tid >> 5] = s;
    __syncthreads();
    if (tid == 0) {
        float t = 0.f;
        #pragma unroll
        for (int i = 0; i < 8; i++) t += red[i];
        bcast = t * (1.0f / CD);
    }
    __syncthreads();
    float mean = bcast;
    __syncthreads();

    float dx = v.x - mean, dy = v.y - mean, dz = v.z - mean, dw = v.w - mean;
    float s2 = dx * dx + dy * dy + dz * dz + dw * dw;
    #pragma unroll
    for (int o = 16; o > 0; o >>= 1) s2 += __shfl_xor_sync(0xffffffffu, s2, o);
    if ((tid & 31) == 0) red[tid >> 5] = s2;
    __syncthreads();
    if (tid == 0) {
        float t = 0.f;
        #pragma unroll
        for (int i = 0; i < 8; i++) t += red[i];
        bcast = rsqrtf(t * (1.0f / CD) + 1e-5f);
    }
    __syncthreads();
    float rs = bcast;

    float4 gg = ((const float4*)g)[tid];
    float4 bb = ((const float4*)b)[tid];
    float o0 = dx * rs * gg.x + bb.x;
    float o1 = dy * rs * gg.y + bb.y;
    float o2 = dz * rs * gg.z + bb.z;
    float o3 = dw * rs * gg.w + bb.w;

    bf16 h0, l0, h1, l1, h2, l2, h3, l3;
    split_bf(o0, h0, l0); split_bf(o1, h1, l1);
    split_bf(o2, h2, l2); split_bf(o3, h3, l3);
    bf162* H = (bf162*)(hh + (size_t)row * CD);
    bf162* L = (bf162*)(hl + (size_t)row * CD);
    bf162 a01, a23, c01, c23;
    a01.x = h0; a01.y = h1; a23.x = h2; a23.y = h3;
    c01.x = l0; c01.y = l1; c23.x = l2; c23.y = l3;
    H[2 * tid] = a01; H[2 * tid + 1] = a23;
    L[2 * tid] = c01; L[2 * tid + 1] = c23;
}

// ---------------- fused embedding + layer-0 LN ----------------
__global__ __launch_bounds__(256) void embed_ln_kernel(
    const int* __restrict__ idx, const float* __restrict__ tok,
    const float* __restrict__ pos, const float* __restrict__ g,
    const float* __restrict__ b, float* __restrict__ x,
    bf16* __restrict__ hh, bf16* __restrict__ hl)
{
    int row = blockIdx.x, tid = threadIdx.x;
    int t = row & (CT - 1);
    int token = idx[row];
    float4 a = ((const float4*)(tok + (size_t)token * CD))[tid];
    float4 p = ((const float4*)(pos + (size_t)t * CD))[tid];
    float4 v;
    v.x = a.x + p.x; v.y = a.y + p.y; v.z = a.z + p.z; v.w = a.w + p.w;
    ((float4*)(x + (size_t)row * CD))[tid] = v;
    ln_rows_body(v, g, b, hh, hl, row, tid);
}

// ---------------- LayerNorm -> bf16 hi/lo planes ----------------
__global__ __launch_bounds__(256) void ln_split_kernel(
    const float* __restrict__ x, const float* __restrict__ g,
    const float* __restrict__ b, bf16* __restrict__ hh, bf16* __restrict__ hl)
{
    int row = blockIdx.x, tid = threadIdx.x;
    float4 v = ((const float4*)(x + (size_t)row * CD))[tid];
    ln_rows_body(v, g, b, hh, hl, row, tid);
}

// ---------------- transpose+split core ----------------
__device__ __forceinline__ void tsplit_body(
    const float* __restrict__ W, bf16* __restrict__ Th, bf16* __restrict__ Tl,
    int K, int N, int n0, int k0)
{
    __shared__ float t[64][65];
    int tid = threadIdx.x;

    int lr = tid >> 4;
    int lc = (tid & 15) << 2;
    #pragma unroll
    for (int s = 0; s < 4; s++) {
        int k = s * 16 + lr;
        float4 v = *(const float4*)(W + (size_t)(k0 + k) * N + n0 + lc);
        t[k][lc] = v.x; t[k][lc + 1] = v.y; t[k][lc + 2] = v.z; t[k][lc + 3] = v.w;
    }
    __syncthreads();

    int n = tid >> 2;
    int kb = (tid & 3) << 4;
    __align__(16) bf16 hi[16];
    __align__(16) bf16 lo[16];
    #pragma unroll
    for (int i = 0; i < 16; i++)
        split_bf(t[kb + i][n], hi[i], lo[i]);
    size_t o = (size_t)(n0 + n) * K + k0 + kb;
    *(uint4*)(Th + o)     = *(uint4*)&hi[0];
    *(uint4*)(Th + o + 8) = *(uint4*)&hi[8];
    *(uint4*)(Tl + o)     = *(uint4*)&lo[0];
    *(uint4*)(Tl + o + 8) = *(uint4*)&lo[8];
}

__global__ __launch_bounds__(256) void tsplit_batch_kernel(
    const float* __restrict__ W, bf16* __restrict__ Th, bf16* __restrict__ Tl,
    int K, int N)
{
    size_t off = (size_t)blockIdx.z * K * N;
    tsplit_body(W + off, Th + off, Tl + off, K, N, blockIdx.x * 64, blockIdx.y * 64);
}

__global__ __launch_bounds__(256) void tsplit_qkv_kernel(
    const float* __restrict__ wq, const float* __restrict__ wk,
    const float* __restrict__ wv, bf16* __restrict__ Th, bf16* __restrict__ Tl)
{
    int z = blockIdx.z;
    int l = z / 3, m = z - 3 * l;
    const float* W = (m == 0 ? wq : (m == 1 ? wk : wv)) + (size_t)l * CD * CD;
    size_t dofs = (size_t)l * 3 * CD * CD + (size_t)m * CD * CD;
    tsplit_body(W, Th + dofs, Tl + dofs, CD, CD, blockIdx.x * 64, blockIdx.y * 64);
}

// ---------------- HMMA bf16x3 GEMM (R7 config: best measured) ----------------
// 128x128 tile, BK=32, 4 warps (2x2), warp tile 64x64, 3-stage cp.async,
// 128 threads, 2 CTAs/SM.
#define GEMM_SMEM (3 * 32768)
#define GEMM_THR 128

__device__ __forceinline__ void gemm_load_stage(
    const bf16* Ah, const bf16* Al, const bf16* Bh, const bf16* Bl,
    int m0, int n0, int K, int k0, uint32_t st, int tid)
{
    #pragma unroll
    for (int i = 0; i < 16; i++) {
        int g = i * GEMM_THR + tid;       // 0..2047 chunks of 16B
        int t4 = g >> 9;
        int r = (g >> 2) & 127;
        int c = g & 3;
        const bf16* src;
        if (t4 == 0)      src = Ah + (size_t)(m0 + r) * K + k0 + c * 8;
        else if (t4 == 1) src = Al + (size_t)(m0 + r) * K + k0 + c * 8;
        else if (t4 == 2) src = Bh + (size_t)(n0 + r) * K + k0 + c * 8;
        else              src = Bl + (size_t)(n0 + r) * K + k0 + c * 8;
        uint32_t off = ((uint32_t)t4 << 13) + (r << 6) + (((uint32_t)(c ^ ((r >> 1) & 3))) << 4);
        cp16(st + off, src);
    }
}

// EPI: 0 plain fp32 | 1 bias+res fp32 | 2 bias+GELU -> bf16 planes | 3 bias fp32
template<int EPI>
__global__ __launch_bounds__(GEMM_THR, 2) void gemm_mma(
    const bf16* __restrict__ Ah, const bf16* __restrict__ Al,
    const bf16* __restrict__ Bh, const bf16* __restrict__ Bl,
    const float* __restrict__ bias, const float* __restrict__ res,
    float* __restrict__ C, bf16* __restrict__ Ch, bf16* __restrict__ Cl,
    int N, int K)
{
    extern __shared__ char smraw[];
    uint32_t sbase = smem_u32(smraw);

    const int tid = threadIdx.x;
    const int m0 = blockIdx.x * 128, n0 = blockIdx.y * 128;
    const int lane = tid & 31, warp = tid >> 5;
    const int wm = (warp >> 1) * 64, wn = (warp & 1) * 64;

    float acc[4][8][4];
    #pragma unroll
    for (int a = 0; a < 4; a++)
        #pragma unroll
        for (int b = 0; b < 8; b++)
            #pragma unroll
            for (int c = 0; c < 4; c++) acc[a][b][c] = 0.f;

    const int NI = K / 32;

    gemm_load_stage(Ah, Al, Bh, Bl, m0, n0, K, 0, sbase, tid);
    CP_COMMIT();
    gemm_load_stage(Ah, Al, Bh, Bl, m0, n0, K, 32, sbase + 32768, tid);
    CP_COMMIT();

    int b2 = 2;
    for (int it = 0; it < NI; it++) {
        CP_WAIT1();
        __syncthreads();
        if (it + 2 < NI)
            gemm_load_stage(Ah, Al, Bh, Bl, m0, n0, K, (it + 2) * 32,
                            sbase + b2 * 32768, tid);
        CP_COMMIT();
        if (++b2 == 3) b2 = 0;

        uint32_t st = sbase + (it - (it / 3) * 3) * 32768;
        #pragma unroll
        for (int c16 = 0; c16 < 2; c16++) {
            uint32_t bH[4][4], bL[4][4];
            #pragma unroll
            for (int jj = 0; jj < 4; jj++) {
                int q = lane >> 3;
                int nr = wn + (jj * 2 + (q >> 1)) * 8 + (lane & 7);
                int ch = (2 * c16 + (q & 1)) ^ ((nr >> 1) & 3);
                uint32_t ad = st + 16384 + (nr << 6) + (ch << 4);
                ldsm4(bH[jj], ad);
                ldsm4(bL[jj], ad + 8192);
            }
            #pragma unroll
            for (int mi = 0; mi < 4; mi++) {
                uint32_t aH[4], aL[4];
                int row = wm + mi * 16 + (lane & 15);
                int ch = (2 * c16 + (lane >> 4)) ^ ((row >> 1) & 3);
                uint32_t ad = st + (row << 6) + (ch << 4);
                ldsm4(aH, ad);
                ldsm4(aL, ad + 8192);
                #pragma unroll
                for (int ni = 0; ni < 8; ni++) {
                    const uint32_t* bh = &bH[ni >> 1][(ni & 1) * 2];
                    const uint32_t* bl = &bL[ni >> 1][(ni & 1) * 2];
                    mma16816(acc[mi][ni], aH, bh);
                    mma16816(acc[mi][ni], aL, bh);
                    mma16816(acc[mi][ni], aH, bl);
                }
            }
        }
    }

    // ---------------- epilogue ----------------
    #pragma unroll
    for (int mi = 0; mi < 4; mi++) {
        #pragma unroll
        for (int ni = 0; ni < 8; ni++) {
            int r0 = m0 + wm + mi * 16 + (lane >> 2);
            int cg = n0 + wn + ni * 8 + (lane & 3) * 2;
            float v0 = acc[mi][ni][0], v1 = acc[mi][ni][1];
            float v2 = acc[mi][ni][2], v3 = acc[mi][ni][3];
            if (EPI == 1 || EPI == 2 || EPI == 3) {
                float b0 = bias[cg], b1 = bias[cg + 1];
                v0 += b0; v1 += b1; v2 += b0; v3 += b1;
            }
            if (EPI == 2) {
                v0 = gelu_f(v0); v1 = gelu_f(v1);
                v2 = gelu_f(v2); v3 = gelu_f(v3);
                bf16 h0, l0, h1, l1;
                bf162 hp, lp;
                split_bf(v0, h0, l0); split_bf(v1, h1, l1);
                hp.x = h0; hp.y = h1; lp.x = l0; lp.y = l1;
                *(bf162*)(Ch + (size_t)r0 * N + cg) = hp;
                *(bf162*)(Cl + (size_t)r0 * N + cg) = lp;
                split_bf(v2, h0, l0); split_bf(v3, h1, l1);
                hp.x = h0; hp.y = h1; lp.x = l0; lp.y = l1;
                *(bf162*)(Ch + (size_t)(r0 + 8) * N + cg) = hp;
                *(bf162*)(Cl + (size_t)(r0 + 8) * N + cg) = lp;
            } else {
                if (EPI == 1) {
                    float2 ra = *(const float2*)(res + (size_t)r0 * N + cg);
                    float2 rb = *(const float2*)(res + (size_t)(r0 + 8) * N + cg);
                    v0 += ra.x; v1 += ra.y; v2 += rb.x; v3 += rb.y;
                }
                float2 w0, w1;
                w0.x = v0; w0.y = v1; w1.x = v2; w1.y = v3;
                *(float2*)(C + (size_t)r0 * N + cg) = w0;
                *(float2*)(C + (size_t)(r0 + 8) * N + cg) = w1;
            }
        }
    }
}

// ---------------- flash attention (fp32, packed QKV, LPT order) ----------------
__global__ __launch_bounds__(256) void attn_kernel(
    const float* __restrict__ QKV, bf16* __restrict__ Yh, bf16* __restrict__ Yl)
{
    extern __shared__ float sm[];
    float* Qst = sm;
    float* Kst = sm + 64 * 64;
    float* Vs  = sm + 2 * 64 * 64;
    float* Pst = sm + 3 * 64 * 64;

    int tid = threadIdx.x;
    int qt = (gridDim.x - 1) - blockIdx.x;   // LPT: longest rows scheduled first
    int bh = blockIdx.y;
    int b = bh >> 4, h = bh & 15;
    int rt = tid >> 4, ct = tid & 15;
    int li = tid >> 2, lf = tid & 3;
    const float scale = 0.125f;

    {
        int t = qt * 64 + li;
        const float* qrow = QKV + (size_t)(b * CT + t) * QKVS + h * CHD;
        #pragma unroll
        for (int u = 0; u < 4; u++) {
            int d4 = lf * 16 + u * 4;
            float4 v = *(const float4*)(qrow + d4);
            Qst[(d4 + 0) * 64 + li] = v.x * scale;
            Qst[(d4 + 1) * 64 + li] = v.y * scale;
            Qst[(d4 + 2) * 64 + li] = v.z * scale;
            Qst[(d4 + 3) * 64 + li] = v.w * scale;
        }
    }

    float m_i[4], l_i[4], o[4][4];
    #pragma unroll
    for (int i = 0; i < 4; i++) {
        m_i[i] = -1e30f; l_i[i] = 0.f;
        #pragma unroll
        for (int d = 0; d < 4; d++) o[i][d] = 0.f;
    }

    for (int kt = 0; kt <= qt; kt++) {
        __syncthreads();
        {
            int t = kt * 64 + li;
            const float* krow = QKV + (size_t)(b * CT + t) * QKVS + CD + h * CHD;
            const float* vrow = QKV + (size_t)(b * CT + t) * QKVS + 2 * CD + h * CHD;
            #pragma unroll
            for (int u = 0; u < 4; u++) {
                int d4 = lf * 16 + u * 4;
                float4 kv = *(const float4*)(krow + d4);
                Kst[(d4 + 0) * 64 + li] = kv.x;
                Kst[(d4 + 1) * 64 + li] = kv.y;
                Kst[(d4 + 2) * 64 + li] = kv.z;
                Kst[(d4 + 3) * 64 + li] = kv.w;
                *(float4*)&Vs[li * 64 + d4] = *(const float4*)(vrow + d4);
            }
        }
        __syncthreads();

        float s[4][4];
        #pragma unroll
        for (int i = 0; i < 4; i++)
            #pragma unroll
            for (int j = 0; j < 4; j++) s[i][j] = 0.f;
        for (int d = 0; d < 64; d++) {
            float a[4], bb[4];
            *(float4*)a  = *(const float4*)&Qst[d * 64 + rt * 4];
            *(float4*)bb = *(const float4*)&Kst[d * 64 + ct * 4];
            #pragma unroll
            for (int i = 0; i < 4; i++)
                #pragma unroll
                for (int j = 0; j < 4; j++)
                    s[i][j] = fmaf(a[i], bb[j], s[i][j]);
        }

        if (kt == qt) {
            #pragma unroll
            for (int i = 0; i < 4; i++)
                #pragma unroll
                for (int j = 0; j < 4; j++)
                    if (ct * 4 + j > rt * 4 + i) s[i][j] = -1e30f;
        }

        #pragma unroll
        for (int i = 0; i < 4; i++) {
            float mx = fmaxf(fmaxf(s[i][0], s[i][1]), fmaxf(s[i][2], s[i][3]));
            #pragma unroll
            for (int off = 1; off < 16; off <<= 1)
                mx = fmaxf(mx, __shfl_xor_sync(0xffffffffu, mx, off));
            float mn = fmaxf(m_i[i], mx);
            float sc = __expf(m_i[i] - mn);
            m_i[i] = mn;
            float ps = 0.f;
            #pragma unroll
            for (int j = 0; j < 4; j++) {
                float p = __expf(s[i][j] - mn);
                s[i][j] = p;
                ps += p;
            }
            #pragma unroll
            for (int off = 1; off < 16; off <<= 1)
                ps += __shfl_xor_sync(0xffffffffu, ps, off);
            l_i[i] = l_i[i] * sc + ps;
            #pragma unroll
            for (int d = 0; d < 4; d++) o[i][d] *= sc;
        }

        #pragma unroll
        for (int i = 0; i < 4; i++)
            #pragma unroll
            for (int j = 0; j < 4; j++)
                Pst[(ct * 4 + j) * 64 + rt * 4 + i] = s[i][j];
        __syncthreads();

        for (int j = 0; j < 64; j++) {
            float p[4], vv[4];
            *(float4*)p  = *(const float4*)&Pst[j * 64 + rt * 4];
            *(float4*)vv = *(const float4*)&Vs[j * 64 + ct * 4];
            #pragma unroll
            for (int i = 0; i < 4; i++)
                #pragma unroll
                for (int d = 0; d < 4; d++)
                    o[i][d] = fmaf(p[i], vv[d], o[i][d]);
        }
    }

    #pragma unroll
    for (int i = 0; i < 4; i++) {
        int t = qt * 64 + rt * 4 + i;
        float inv = 1.0f / l_i[i];
        size_t off = (size_t)(b * CT + t) * CD + h * CHD + ct * 4;
        bf16 h0, l0, h1, l1, h2, l2, h3, l3;
        split_bf(o[i][0] * inv, h0, l0);
        split_bf(o[i][1] * inv, h1, l1);
        split_bf(o[i][2] * inv, h2, l2);
        split_bf(o[i][3] * inv, h3, l3);
        bf162 a01, a23, c01, c23;
        a01.x = h0; a01.y = h1; a23.x = h2; a23.y = h3;
        c01.x = l0; c01.y = l1; c23.x = l2; c23.y = l3;
        ((bf162*)(Yh + off))[0] = a01; ((bf162*)(Yh + off))[1] = a23;
        ((bf162*)(Yl + off))[0] = c01; ((bf162*)(Yl + off))[1] = c23;
    }
}

// ---------------- host ----------------
extern "C" void kernel_launch(void* const* d_in, const int* in_sizes, int n_in,
                              void* d_out, int out_size)
{
    (void)in_sizes; (void)n_in; (void)out_size;

    const int*   idx     = (const int*)  d_in[0];
    const float* tok_emb = (const float*)d_in[1];
    const float* pos_emb = (const float*)d_in[2];
    const float* wq      = (const float*)d_in[3];
    const float* wk      = (const float*)d_in[4];
    const float* wv      = (const float*)d_in[5];
    const float* wo      = (const float*)d_in[6];
    const float* bo      = (const float*)d_in[7];
    const float* ln1_g   = (const float*)d_in[8];
    const float* ln1_b   = (const float*)d_in[9];
    const float* ln2_g   = (const float*)d_in[10];
    const float* ln2_b   = (const float*)d_in[11];
    const float* w1      = (const float*)d_in[12];
    const float* b1      = (const float*)d_in[13];
    const float* w2      = (const float*)d_in[14];
    const float* b2      = (const float*)d_in[15];
    const float* lnf_g   = (const float*)d_in[16];
    const float* lnf_b   = (const float*)d_in[17];
    const float* w_head  = (const float*)d_in[18];
    const float* b_head  = (const float*)d_in[19];
    float* out = (float*)d_out;

    float *x, *qkv;
    bf16 *hh, *hl, *yh, *yl, *fh, *fl;
    bf16 *qkvh, *qkvl, *oh, *ol, *h1h, *h1l, *h2h, *h2l, *hdh, *hdl;
    cudaGetSymbolAddress((void**)&x, g_x);
    cudaGetSymbolAddress((void**)&qkv, g_qkv);
    cudaGetSymbolAddress((void**)&hh, g_hh);
    cudaGetSymbolAddress((void**)&hl, g_hl);
    cudaGetSymbolAddress((void**)&yh, g_yh);
    cudaGetSymbolAddress((void**)&yl, g_yl);
    cudaGetSymbolAddress((void**)&fh, g_fh);
    cudaGetSymbolAddress((void**)&fl, g_fl);
    cudaGetSymbolAddress((void**)&qkvh, t_qkvh);
    cudaGetSymbolAddress((void**)&qkvl, t_qkvl);
    cudaGetSymbolAddress((void**)&oh, t_oh);
    cudaGetSymbolAddress((void**)&ol, t_ol);
    cudaGetSymbolAddress((void**)&h1h, t_1h);
    cudaGetSymbolAddress((void**)&h1l, t_1l);
    cudaGetSymbolAddress((void**)&h2h, t_2h);
    cudaGetSymbolAddress((void**)&h2l, t_2l);
    cudaGetSymbolAddress((void**)&hdh, t_hdh);
    cudaGetSymbolAddress((void**)&hdl, t_hdl);

    cudaFuncSetAttribute(attn_kernel, cudaFuncAttributeMaxDynamicSharedMemorySize, 65536);
    cudaFuncSetAttribute(gemm_mma<0>, cudaFuncAttributeMaxDynamicSharedMemorySize, GEMM_SMEM);
    cudaFuncSetAttribute(gemm_mma<1>, cudaFuncAttributeMaxDynamicSharedMemorySize, GEMM_SMEM);
    cudaFuncSetAttribute(gemm_mma<2>, cudaFuncAttributeMaxDynamicSharedMemorySize, GEMM_SMEM);
    cudaFuncSetAttribute(gemm_mma<3>, cudaFuncAttributeMaxDynamicSharedMemorySize, GEMM_SMEM);

    dim3 gQKV(CM / 128, QKVS / 128);
    dim3 gDD(CM / 128, CD / 128);
    dim3 gDF(CM / 128, CF / 128);
    dim3 gDV(CM / 128, CV / 128);
    dim3 gAt(CT / 64, CB * CH);

    // launch 0: qkv weight planes
    tsplit_qkv_kernel<<<dim3(CD / 64, CD / 64, 3 * CL), 256>>>(wq, wk, wv, qkvh, qkvl);
    // launch 1: fused embed + layer-0 LN
    embed_ln_kernel<<<CM, 256>>>(idx, tok_emb, pos_emb, ln1_g, ln1_b, x, hh, hl);
    // launch 2: layer-0 QKV GEMM
    gemm_mma<0><<<gQKV, GEMM_THR, GEMM_SMEM>>>(hh, hl, qkvh, qkvl,
                                               nullptr, nullptr, qkv, nullptr, nullptr,
                                               QKVS, CD);
    // launch 3: PROFILED — layer-0 attention
    attn_kernel<<<gAt, 256, 65536>>>(qkv, yh, yl);
    // remaining prepass (batched)
    tsplit_batch_kernel<<<dim3(CD / 64, CD / 64, CL), 256>>>(wo, oh, ol, CD, CD);
    tsplit_batch_kernel<<<dim3(CF / 64, CD / 64, CL), 256>>>(w1, h1h, h1l, CD, CF);
    tsplit_batch_kernel<<<dim3(CD / 64, CF / 64, CL), 256>>>(w2, h2h, h2l, CF, CD);
    tsplit_batch_kernel<<<dim3(CV / 64, CD / 64, 1), 256>>>(w_head, hdh, hdl, CD, CV);

    for (int l = 0; l < CL; l++) {
        size_t wo4 = (size_t)l * CD * CD;
        size_t p3 = (size_t)l * 3 * CD * CD;
        size_t w1o = (size_t)l * CD * CF;
        if (l > 0) {
            ln_split_kernel<<<CM, 256>>>(x, ln1_g + l * CD, ln1_b + l * CD, hh, hl);
            gemm_mma<0><<<gQKV, GEMM_THR, GEMM_SMEM>>>(hh, hl, qkvh + p3, qkvl + p3,
                                                       nullptr, nullptr, qkv, nullptr, nullptr,
                                                       QKVS, CD);
            attn_kernel<<<gAt, 256, 65536>>>(qkv, yh, yl);
        }
        gemm_mma<1><<<gDD, GEMM_THR, GEMM_SMEM>>>(yh, yl, oh + wo4, ol + wo4,
                                                  bo + l * CD, x, x, nullptr, nullptr, CD, CD);
        ln_split_kernel<<<CM, 256>>>(x, ln2_g + l * CD, ln2_b + l * CD, hh, hl);
        gemm_mma<2><<<gDF, GEMM_THR, GEMM_SMEM>>>(hh, hl, h1h + w1o, h1l + w1o,
                                                  b1 + (size_t)l * CF, nullptr,
                                                  nullptr, fh, fl, CF, CD);
        gemm_mma<1><<<gDD, GEMM_THR, GEMM_SMEM>>>(fh, fl, h2h + w1o, h2l + w1o,
                                                  b2 + l * CD, x, x, nullptr, nullptr, CD, CF);
    }

    ln_split_kernel<<<CM, 256>>>(x, lnf_g, lnf_b, hh, hl);
    gemm_mma<3><<<gDV, GEMM_THR, GEMM_SMEM>>>(hh, hl, hdh, hdl,
                                              b_head, nullptr, out, nullptr, nullptr, CV, CD);
}